// round 9
// baseline (speedup 1.0000x reference)
#include <cuda_runtime.h>
#include <math.h>

#define NJ 17
#define NP 14
#define NC 59          // 17 joint channels + 14*3 pair channels
#define GRID 64

__constant__ int c_pj[NP] = {0,1,2,0,4,5,0,8,14,15,8,11,12,8};
__constant__ int c_cj[NP] = {1,2,3,4,5,6,8,14,15,16,11,12,13,10};

// Transposed scratch: g_scratch[c * 256 + b] so the finalize kernel
// (one thread per b) reads fully coalesced rows. Plus per-b l3d partials.
__device__ float g_scratch[NC * 256];
__device__ float g_l3d[256];

__device__ __forceinline__ float warp_red_f(float v) {
#pragma unroll
    for (int o = 16; o > 0; o >>= 1) v += __shfl_down_sync(0xffffffffu, v, o);
    return v;
}

// One block per (b, c). c < 17 : L2D joint channel.  c >= 17 : pair channel.
// Reads the 4096-float slab middle_out[b][c] once; GT built from separable
// 64-entry Gaussian vectors in smem (exp count = 128/joint, not 4096).
// Blocks with c==0 additionally compute the per-b l3d partial (tiny).
__global__ __launch_bounds__(256) void mpjpe_main_kernel(
    const float* __restrict__ pred,
    const float* __restrict__ joints,
    const float* __restrict__ middle_out,
    const float* __restrict__ joint2d)
{
    const int b = blockIdx.x;
    const int c = blockIdx.y;
    const int t = threadIdx.x;

    __shared__ __align__(16) float exA[64], eyA[64], exB[64], eyB[64];
    __shared__ float warp_sums[8];
    __shared__ float l3s[51];

    float ca, cb;       // GT = ca*hp + cb*hc  (ca,cb in {0,1})
    int jA, jB;
    if (c < NJ) {
        jA = c; jB = 0;
        ca = 1.f; cb = 0.f;
    } else {
        const int p  = (c - NJ) / 3;
        const int ch = (c - NJ) % 3;
        jA = c_pj[p];
        jB = c_cj[p];
        const float d = joints[(b * NJ + jA) * 3 + 2] - joints[(b * NJ + jB) * 3 + 2];
        // r = where(d > eps, 1, where(|d| < eps, 0, -1)), eps = 0.1
        const int r = (d > 0.1f) ? 1 : ((fabsf(d) < 0.1f) ? 0 : -1);
        ca = (ch == 1) ? 1.f : 0.f;                           // hp appears only in ch1
        cb = ((ch == 0 && r == -1) ||
              (ch == 1 && r ==  0) ||
              (ch == 2 && r ==  1)) ? 1.f : 0.f;              // hc per r
    }

    // Build normalized separable Gaussian vectors.
    // grp 0: exA, 1: eyA, 2: exB, 3: eyB  (64 threads each)
    {
        const int lane = t & 63;
        const int grp  = t >> 6;
        const int jj   = (grp < 2) ? jA : jB;
        const int axis = grp & 1;                 // 0 -> x (H axis), 1 -> y (W axis)
        const float x  = joint2d[(b * NJ + jj) * 2 + axis] * 64.f;
        float rx = rintf(x);
        rx = fminf(fmaxf(rx, 0.f), 63.f);
        const float mind = (rx - x) * (rx - x);   // min over grid of (i-x)^2
        const float dd = (float)lane - x;
        float v = expf((mind - dd * dd) * 0.25f); // <= 1, exact max-normalization
        if (c < NJ && grp >= 2) v = 0.f;          // unused child vectors in joint mode
        float* dst = (grp == 0) ? exA : (grp == 1) ? eyA : (grp == 2) ? exB : eyB;
        dst[lane] = v;
    }
    __syncthreads();

    // Stream the 16 KB channel slab. Front-batch all 4 float4 loads (MLP_p1=4)
    // before any math so DRAM latency overlaps across the batch.
    const float4* mo4 =
        reinterpret_cast<const float4*>(middle_out) + ((size_t)b * NC + c) * 1024;

    float4 m[4];
#pragma unroll
    for (int it = 0; it < 4; it++) m[it] = mo4[t + it * 256];

    const float4 eA = reinterpret_cast<const float4*>(eyA)[t & 15];
    const float4 eB = reinterpret_cast<const float4*>(eyB)[t & 15];

    float acc = 0.f;
#pragma unroll
    for (int it = 0; it < 4; it++) {
        const int q = t + it * 256;          // q in [0,1024): float4 index
        const int h = q >> 4;                // row (H axis)
        const float gA = ca * exA[h];
        const float gB = cb * exB[h];
        const float d0 = m[it].x - (gA * eA.x + gB * eB.x);
        const float d1 = m[it].y - (gA * eA.y + gB * eB.y);
        const float d2 = m[it].z - (gA * eA.z + gB * eB.z);
        const float d3 = m[it].w - (gA * eA.w + gB * eB.w);
        acc += d0 * d0 + d1 * d1 + d2 * d2 + d3 * d3;
    }

    acc = warp_red_f(acc);
    if ((t & 31) == 0) warp_sums[t >> 5] = acc;

    // Per-b l3d partial (only the c==0 block for this b): 51 |diffs|.
    if (c == 0 && t < 51)
        l3s[t] = fabsf(joints[b * 51 + t] - pred[b * 51 + t]);

    __syncthreads();
    if (t < 8) {
        float v = warp_sums[t];
#pragma unroll
        for (int o = 4; o > 0; o >>= 1) v += __shfl_down_sync(0xffu, v, o);
        if (t == 0) g_scratch[c * 256 + b] = v;   // transposed write
    }
    if (c == 0 && t == 32) {        // different warp than the t<8 reduction
        float s = 0.f;
#pragma unroll
        for (int i = 0; i < 51; i++) s += l3s[i];
        g_l3d[b] = s;
    }
}

// One thread per batch element; scratch layout is [c][b] so every LDG below is
// fully coalesced (1 wavefront each instead of 32). Per-b combine in fp32,
// single conversion to double, one 256-wide double reduction.
__global__ __launch_bounds__(256) void mpjpe_final_kernel(
    float* __restrict__ out, int B)
{
    const int t = threadIdx.x;
    double db = 0.0;

    if (t < B) {
        float l2 = 0.f;
#pragma unroll
        for (int j = 0; j < NJ; j++) l2 += g_scratch[j * 256 + t];
        float lh = 0.f;
#pragma unroll
        for (int p = 0; p < NP; p++) {
            const int base = (NJ + p * 3) * 256 + t;
            const float n = sqrtf(g_scratch[base]) +
                            sqrtf(g_scratch[base + 256]) +
                            sqrtf(g_scratch[base + 512]);
            lh += n * n;
        }
        db = (double)g_l3d[t] + 0.005 * ((double)lh + (double)l2);
    }

#pragma unroll
    for (int o = 16; o > 0; o >>= 1) db += __shfl_down_sync(0xffffffffu, db, o);
    __shared__ double sm[8];
    if ((t & 31) == 0) sm[t >> 5] = db;
    __syncthreads();
    if (t == 0) {
        double sum = 0.0;
        for (int w = 0; w < 8; w++) sum += sm[w];
        out[0] = (float)(sum / (double)B);
    }
}

extern "C" void kernel_launch(void* const* d_in, const int* in_sizes, int n_in,
                              void* d_out, int out_size)
{
    const float* pred   = (const float*)d_in[0];
    const float* joints = (const float*)d_in[1];
    const float* mo     = (const float*)d_in[2];
    const float* j2d    = (const float*)d_in[3];

    int B = in_sizes[0] / (NJ * 3);
    if (B > 256) B = 256;   // scratch capacity guard (problem uses B=256)

    dim3 grid(B, NC);
    mpjpe_main_kernel<<<grid, 256>>>(pred, joints, mo, j2d);
    mpjpe_final_kernel<<<1, 256>>>((float*)d_out, B);
}

// round 10
// speedup vs baseline: 1.3232x; 1.3232x over previous
#include <cuda_runtime.h>
#include <math.h>

#define NJ 17
#define NP 14
#define NC 59          // 17 joint channels + 14*3 pair channels
#define GRID 64

__constant__ int c_pj[NP] = {0,1,2,0,4,5,0,8,14,15,8,11,12,8};
__constant__ int c_cj[NP] = {1,2,3,4,5,6,8,14,15,16,11,12,13,10};

// g_scratch[b*NC + c]: per-(b,channel) sum of squared diffs (contiguous per b).
__device__ float  g_scratch[256 * NC];
__device__ double g_perb[256];
__device__ int    g_cnt_b[256];   // zero-initialized; self-resetting each launch
__device__ int    g_cnt_all;      // zero-initialized; self-resetting each launch

__device__ __forceinline__ float warp_red_f(float v) {
#pragma unroll
    for (int o = 16; o > 0; o >>= 1) v += __shfl_down_sync(0xffffffffu, v, o);
    return v;
}

// Single fused kernel. One block per (b, c): stream the 16 KB channel slab,
// accumulate sum((mo - GT)^2) with GT built from separable max-normalized
// Gaussian vectors (128 exps/joint, not 4096). Epilogue via atomic counters:
// last-of-59 block per b combines that b's losses; last-of-256 winner block
// reduces the 256 per-b doubles and writes the scalar output.
__global__ __launch_bounds__(256) void mpjpe_fused_kernel(
    const float* __restrict__ pred,
    const float* __restrict__ joints,
    const float* __restrict__ middle_out,
    const float* __restrict__ joint2d,
    float* __restrict__ out, int B)
{
    const int b = blockIdx.x;
    const int c = blockIdx.y;
    const int t = threadIdx.x;

    __shared__ __align__(16) float exA[64], eyA[64], exB[64], eyB[64];
    __shared__ float warp_sums[8];
    __shared__ int   s_last_all;
    if (t == 0) s_last_all = 0;

    float ca, cb;       // GT = ca*hp + cb*hc  (ca,cb in {0,1})
    int jA, jB;
    if (c < NJ) {
        jA = c; jB = 0;
        ca = 1.f; cb = 0.f;
    } else {
        const int p  = (c - NJ) / 3;
        const int ch = (c - NJ) % 3;
        jA = c_pj[p];
        jB = c_cj[p];
        const float d = joints[(b * NJ + jA) * 3 + 2] - joints[(b * NJ + jB) * 3 + 2];
        // r = where(d > eps, 1, where(|d| < eps, 0, -1)), eps = 0.1
        const int r = (d > 0.1f) ? 1 : ((fabsf(d) < 0.1f) ? 0 : -1);
        ca = (ch == 1) ? 1.f : 0.f;                           // hp appears only in ch1
        cb = ((ch == 0 && r == -1) ||
              (ch == 1 && r ==  0) ||
              (ch == 2 && r ==  1)) ? 1.f : 0.f;              // hc per r
    }

    // Build normalized separable Gaussian vectors.
    // grp 0: exA, 1: eyA, 2: exB, 3: eyB  (64 threads each)
    {
        const int lane = t & 63;
        const int grp  = t >> 6;
        const int jj   = (grp < 2) ? jA : jB;
        const int axis = grp & 1;                 // 0 -> x (H axis), 1 -> y (W axis)
        const float x  = joint2d[(b * NJ + jj) * 2 + axis] * 64.f;
        float rx = rintf(x);
        rx = fminf(fmaxf(rx, 0.f), 63.f);
        const float mind = (rx - x) * (rx - x);   // min over grid of (i-x)^2
        const float dd = (float)lane - x;
        float v = expf((mind - dd * dd) * 0.25f); // <= 1, exact max-normalization
        if (c < NJ && grp >= 2) v = 0.f;          // unused child vectors in joint mode
        float* dst = (grp == 0) ? exA : (grp == 1) ? eyA : (grp == 2) ? exB : eyB;
        dst[lane] = v;
    }
    __syncthreads();

    // Stream the 16 KB channel slab. Front-batch all 4 float4 loads (MLP_p1=4).
    const float4* mo4 =
        reinterpret_cast<const float4*>(middle_out) + ((size_t)b * NC + c) * 1024;

    float4 m[4];
#pragma unroll
    for (int it = 0; it < 4; it++) m[it] = mo4[t + it * 256];

    const float4 eA = reinterpret_cast<const float4*>(eyA)[t & 15];
    const float4 eB = reinterpret_cast<const float4*>(eyB)[t & 15];

    float acc = 0.f;
#pragma unroll
    for (int it = 0; it < 4; it++) {
        const int q = t + it * 256;          // q in [0,1024): float4 index
        const int h = q >> 4;                // row (H axis)
        const float gA = ca * exA[h];
        const float gB = cb * exB[h];
        const float d0 = m[it].x - (gA * eA.x + gB * eB.x);
        const float d1 = m[it].y - (gA * eA.y + gB * eB.y);
        const float d2 = m[it].z - (gA * eA.z + gB * eB.z);
        const float d3 = m[it].w - (gA * eA.w + gB * eB.w);
        acc += d0 * d0 + d1 * d1 + d2 * d2 + d3 * d3;
    }

    acc = warp_red_f(acc);
    if ((t & 31) == 0) warp_sums[t >> 5] = acc;
    __syncthreads();

    if (t == 0) {
        float v = 0.f;
#pragma unroll
        for (int w = 0; w < 8; w++) v += warp_sums[w];
        g_scratch[b * NC + c] = v;
        __threadfence();                           // publish before arrival
        const int old = atomicAdd(&g_cnt_b[b], 1);
        if (old == NC - 1) {
            // All 59 channels of b are published. Combine this b.
            __threadfence();
            const float* s = &g_scratch[b * NC];
            float l2 = 0.f;
#pragma unroll
            for (int j = 0; j < NJ; j++) l2 += __ldcg(&s[j]);
            float lh = 0.f;
#pragma unroll
            for (int p = 0; p < NP; p++) {
                const float n = sqrtf(__ldcg(&s[NJ + p * 3])) +
                                sqrtf(__ldcg(&s[NJ + p * 3 + 1])) +
                                sqrtf(__ldcg(&s[NJ + p * 3 + 2]));
                lh += n * n;
            }
            float l3 = 0.f;
#pragma unroll
            for (int i = 0; i < NJ * 3; i++)
                l3 += fabsf(joints[b * (NJ * 3) + i] - pred[b * (NJ * 3) + i]);

            g_perb[b]  = (double)l3 + 0.005 * ((double)lh + (double)l2);
            g_cnt_b[b] = 0;                        // reset for next graph replay
            __threadfence();
            const int o2 = atomicAdd(&g_cnt_all, 1);
            if (o2 == B - 1) s_last_all = 1;       // this block runs the final reduce
        }
    }
    __syncthreads();

    if (s_last_all) {
        // All B per-b doubles are published (each preceded by a threadfence).
        double db = (t < B) ? __ldcg(&g_perb[t]) : 0.0;
#pragma unroll
        for (int o = 16; o > 0; o >>= 1) db += __shfl_down_sync(0xffffffffu, db, o);
        __shared__ double sm[8];
        if ((t & 31) == 0) sm[t >> 5] = db;
        __syncthreads();
        if (t == 0) {
            double sum = 0.0;
            for (int w = 0; w < 8; w++) sum += sm[w];
            out[0] = (float)(sum / (double)B);
            g_cnt_all = 0;                         // reset for next graph replay
        }
    }
}

extern "C" void kernel_launch(void* const* d_in, const int* in_sizes, int n_in,
                              void* d_out, int out_size)
{
    const float* pred   = (const float*)d_in[0];
    const float* joints = (const float*)d_in[1];
    const float* mo     = (const float*)d_in[2];
    const float* j2d    = (const float*)d_in[3];

    int B = in_sizes[0] / (NJ * 3);
    if (B > 256) B = 256;   // scratch capacity guard (problem uses B=256)

    dim3 grid(B, NC);
    mpjpe_fused_kernel<<<grid, 256>>>(pred, joints, mo, j2d, (float*)d_out, B);
}

// round 12
// speedup vs baseline: 1.5920x; 1.2031x over previous
#include <cuda_runtime.h>
#include <math.h>

#define NJ 17
#define NP 14
#define NC 59          // 17 joint channels + 14*3 pair channels

__constant__ int c_pj[NP] = {0,1,2,0,4,5,0,8,14,15,8,11,12,8};
__constant__ int c_cj[NP] = {1,2,3,4,5,6,8,14,15,16,11,12,13,10};

// One double partial per block (B*4 blocks), plus completion counter.
__device__ double g_part[256 * 4];
__device__ int    g_cnt;          // zero-initialized; self-resets each launch

__device__ __forceinline__ float warp_red_f(float v) {
#pragma unroll
    for (int o = 16; o > 0; o >>= 1) v += __shfl_down_sync(0xffffffffu, v, o);
    return v;
}

// Grid (B, 4). Block (b,g) owns a pair-aligned channel group:
//   g=0: channels 0..16  (all 17 joint channels, + l3d for this b)
//   g=1: channels 17..31 (pairs 0..4)
//   g=2: channels 32..46 (pairs 5..9)
//   g=3: channels 47..58 (pairs 10..13)
// Prologue builds ALL 34 separable Gaussian vectors once per block with
// hardware __expf (MUFU), then the channel loop is a pure DRAM stream.
// Each block emits one double loss partial; last block reduces all of them.
__global__ __launch_bounds__(256) void mpjpe_fused_kernel(
    const float* __restrict__ pred,
    const float* __restrict__ joints,
    const float* __restrict__ middle_out,
    const float* __restrict__ joint2d,
    float* __restrict__ out, int B)
{
    const int b = blockIdx.x;
    const int g = blockIdx.y;
    const int t = threadIdx.x;
    const int w = t >> 5;

    const int c0  = (g == 0) ? 0  : 17 + (g - 1) * 15;
    const int nch = (g == 0) ? 17 : (g == 3) ? 12 : 15;

    __shared__ __align__(16) float heat[34 * 64];  // [j*2+axis][64]
    __shared__ float wsum[8][20];                  // [warp][channel] padded
    __shared__ float chan[17];
    __shared__ float l3s[51];
    __shared__ int   s_win;
    if (t == 0) s_win = 0;

    // All 34 max-normalized Gaussian vectors: 2176 hardware exps (~9/thread).
    for (int idx = t; idx < 34 * 64; idx += 256) {
        const int v = idx >> 6, lane = idx & 63;
        const int j = v >> 1, axis = v & 1;
        const float x  = joint2d[(b * NJ + j) * 2 + axis] * 64.f;
        const float rx = fminf(fmaxf(rintf(x), 0.f), 63.f);
        const float mind = (rx - x) * (rx - x);    // min over grid of (i-x)^2
        const float dd = (float)lane - x;
        heat[idx] = __expf((mind - dd * dd) * 0.25f);  // exact max-normalization
    }
    if (g == 0 && t < 51)
        l3s[t] = fabsf(joints[b * 51 + t] - pred[b * 51 + t]);
    __syncthreads();

    const float4* mobase =
        reinterpret_cast<const float4*>(middle_out) + ((size_t)b * NC + c0) * 1024;

    for (int i = 0; i < nch; i++) {
        const int c = c0 + i;

        // Front-batch the 4 float4 loads for this 16 KB channel slab.
        const float4 m0 = mobase[i * 1024 + t];
        const float4 m1 = mobase[i * 1024 + t + 256];
        const float4 m2 = mobase[i * 1024 + t + 512];
        const float4 m3 = mobase[i * 1024 + t + 768];

        float ca, cb;          // GT = ca*hp + cb*hc, ca/cb in {0,1}
        int jA, jB;
        if (c < NJ) {
            jA = c; jB = 0; ca = 1.f; cb = 0.f;
        } else {
            const int p  = (c - NJ) / 3;
            const int ch = (c - NJ) % 3;
            jA = c_pj[p]; jB = c_cj[p];
            const float d = joints[(b * NJ + jA) * 3 + 2] -
                            joints[(b * NJ + jB) * 3 + 2];
            const int r = (d > 0.1f) ? 1 : ((fabsf(d) < 0.1f) ? 0 : -1);
            ca = (ch == 1) ? 1.f : 0.f;
            cb = ((ch == 0 && r == -1) ||
                  (ch == 1 && r ==  0) ||
                  (ch == 2 && r ==  1)) ? 1.f : 0.f;
        }
        const float* exA = &heat[(jA * 2 + 0) * 64];
        const float* eyA = &heat[(jA * 2 + 1) * 64];
        const float* exB = &heat[(jB * 2 + 0) * 64];
        const float* eyB = &heat[(jB * 2 + 1) * 64];
        const float4 eA = reinterpret_cast<const float4*>(eyA)[t & 15];
        const float4 eB = reinterpret_cast<const float4*>(eyB)[t & 15];

        const int h0 = t >> 4;      // rows for m0..m3 are h0, h0+16, +32, +48
        float acc = 0.f;
        {
            const float gA = ca * exA[h0],      gB = cb * exB[h0];
            const float d0 = m0.x - (gA*eA.x + gB*eB.x), d1 = m0.y - (gA*eA.y + gB*eB.y);
            const float d2 = m0.z - (gA*eA.z + gB*eB.z), d3 = m0.w - (gA*eA.w + gB*eB.w);
            acc += d0*d0 + d1*d1 + d2*d2 + d3*d3;
        }
        {
            const float gA = ca * exA[h0 + 16], gB = cb * exB[h0 + 16];
            const float d0 = m1.x - (gA*eA.x + gB*eB.x), d1 = m1.y - (gA*eA.y + gB*eB.y);
            const float d2 = m1.z - (gA*eA.z + gB*eB.z), d3 = m1.w - (gA*eA.w + gB*eB.w);
            acc += d0*d0 + d1*d1 + d2*d2 + d3*d3;
        }
        {
            const float gA = ca * exA[h0 + 32], gB = cb * exB[h0 + 32];
            const float d0 = m2.x - (gA*eA.x + gB*eB.x), d1 = m2.y - (gA*eA.y + gB*eB.y);
            const float d2 = m2.z - (gA*eA.z + gB*eB.z), d3 = m2.w - (gA*eA.w + gB*eB.w);
            acc += d0*d0 + d1*d1 + d2*d2 + d3*d3;
        }
        {
            const float gA = ca * exA[h0 + 48], gB = cb * exB[h0 + 48];
            const float d0 = m3.x - (gA*eA.x + gB*eB.x), d1 = m3.y - (gA*eA.y + gB*eB.y);
            const float d2 = m3.z - (gA*eA.z + gB*eB.z), d3 = m3.w - (gA*eA.w + gB*eB.w);
            acc += d0*d0 + d1*d1 + d2*d2 + d3*d3;
        }

        acc = warp_red_f(acc);
        if ((t & 31) == 0) wsum[w][i] = acc;   // disjoint slots: no sync in loop
    }
    __syncthreads();

    if (t < nch) {
        float s = 0.f;
#pragma unroll
        for (int ww = 0; ww < 8; ww++) s += wsum[ww][t];
        chan[t] = s;
    }
    __syncthreads();

    if (t == 0) {
        double part;
        if (g == 0) {
            float l3 = 0.f;
#pragma unroll
            for (int i = 0; i < 51; i++) l3 += l3s[i];
            float l2 = 0.f;
#pragma unroll
            for (int j = 0; j < NJ; j++) l2 += chan[j];
            part = (double)l3 + 0.005 * (double)l2;
        } else {
            float lh = 0.f;
            for (int k = 0; k < nch; k += 3) {
                const float n = sqrtf(chan[k]) + sqrtf(chan[k+1]) + sqrtf(chan[k+2]);
                lh += n * n;
            }
            part = 0.005 * (double)lh;
        }
        g_part[b * 4 + g] = part;
        __threadfence();                       // publish before arrival
        const int old = atomicAdd(&g_cnt, 1);
        if (old == 4 * B - 1) s_win = 1;       // this block performs final reduce
    }
    __syncthreads();

    if (s_win) {
        __threadfence();                       // acquire published partials
        double db = 0.0;
        for (int idx = t; idx < 4 * B; idx += 256) db += __ldcg(&g_part[idx]);
#pragma unroll
        for (int o = 16; o > 0; o >>= 1) db += __shfl_down_sync(0xffffffffu, db, o);
        __shared__ double sm[8];
        if ((t & 31) == 0) sm[t >> 5] = db;
        __syncthreads();
        if (t == 0) {
            double sum = 0.0;
            for (int ww = 0; ww < 8; ww++) sum += sm[ww];
            out[0] = (float)(sum / (double)B);
            g_cnt = 0;                         // reset for next graph replay
        }
    }
}

extern "C" void kernel_launch(void* const* d_in, const int* in_sizes, int n_in,
                              void* d_out, int out_size)
{
    const float* pred   = (const float*)d_in[0];
    const float* joints = (const float*)d_in[1];
    const float* mo     = (const float*)d_in[2];
    const float* j2d    = (const float*)d_in[3];

    int B = in_sizes[0] / (NJ * 3);
    if (B > 256) B = 256;   // scratch capacity guard (problem uses B=256)

    dim3 grid(B, 4);
    mpjpe_fused_kernel<<<grid, 256>>>(pred, joints, mo, j2d, (float*)d_out, B);
}